// round 9
// baseline (speedup 1.0000x reference)
#include <cuda_runtime.h>
#include <cuda_fp16.h>
#include <mma.h>

using namespace nvcuda;

#define MAXN 100000
#define MAXE 1600000
#define PADE (MAXE + 7 * MAXN)   // padded CSC capacity
#define MAXG 64
#define SENT MAXN                // sentinel node index (zero feature row)

__device__ __align__(128) float  g_dinv[MAXN];
__device__ __align__(128) int    g_deg[MAXN];
__device__ __align__(128) int    g_rowptr[MAXN];
__device__ __align__(128) int    g_cursor[MAXN];
__device__ __align__(128) int    g_aux[128];
__device__ __align__(128) int    g_esrc[PADE];          // CSC src, sentinel-padded
__device__ __align__(128) __half g_h[MAXN * 64 + 64];   // +sentinel row
__device__ __align__(128) __half g_a[MAXN * 64];
__device__ __align__(128) float  g_sums[MAXG * 32];
__device__ __align__(128) float  g_cnt[MAXG];

// ---------------------------------------------------------------------------
// zero deg/sums/cnt + prefill esrc with sentinel
__global__ void k_zero(int* deg, float* sums, float* cnt, int* esrc, int N, int G) {
    int i = blockIdx.x * blockDim.x + threadIdx.x;
    if (i < N) deg[i] = 0;
    if (i < G * 32) sums[i] = 0.0f;
    if (i < G) cnt[i] = 0.0f;
    if (i < PADE) esrc[i] = SENT;
}

// degree histogram + graph-size histogram
__global__ void k_hist(const int* __restrict__ dst, const int* __restrict__ batch,
                       int* deg, float* cnt, int E, int N) {
    int e = blockIdx.x * blockDim.x + threadIdx.x;
    if (e < E) atomicAdd(&deg[dst[e]], 1);
    if (e < N) atomicAdd(&cnt[batch[e]], 1.0f);
}

// --- exclusive scan of PADDED deg -> rowptr (shuffle-based) -----------------
__global__ void k_scan1(const int* __restrict__ deg, int* rowptr, int* aux, int N) {
    __shared__ int wsum[32];
    int i = blockIdx.x * 1024 + threadIdx.x;
    int lane = threadIdx.x & 31, warp = threadIdx.x >> 5;
    int v = 0;
    if (i < N) v = ((deg[i] + 7) >> 3) << 3;    // pad to multiple of 8
    int incl = v;
#pragma unroll
    for (int off = 1; off < 32; off <<= 1) {
        int t = __shfl_up_sync(0xffffffff, incl, off);
        if (lane >= off) incl += t;
    }
    if (lane == 31) wsum[warp] = incl;
    __syncthreads();
    if (warp == 0) {
        int w = wsum[lane];
        int wi = w;
#pragma unroll
        for (int off = 1; off < 32; off <<= 1) {
            int t = __shfl_up_sync(0xffffffff, wi, off);
            if (lane >= off) wi += t;
        }
        wsum[lane] = wi - w;                    // exclusive warp offsets
        if (lane == 31) aux[blockIdx.x] = wi;   // block total
    }
    __syncthreads();
    if (i < N) rowptr[i] = incl - v + wsum[warp];
}

__global__ void k_scan2(int* aux, int nb) {
    __shared__ int s[128];
    int v = (threadIdx.x < nb) ? aux[threadIdx.x] : 0;
    s[threadIdx.x] = v;
    __syncthreads();
    for (int off = 1; off < 128; off <<= 1) {
        int t = (threadIdx.x >= off) ? s[threadIdx.x - off] : 0;
        __syncthreads();
        s[threadIdx.x] += t;
        __syncthreads();
    }
    if (threadIdx.x < nb) aux[threadIdx.x] = s[threadIdx.x] - v;
}

// scan finalize + dinv (fused)
__global__ void k_scan3(int* rowptr, int* cursor, const int* __restrict__ aux,
                        const int* __restrict__ deg, float* dinv, int N) {
    int i = blockIdx.x * blockDim.x + threadIdx.x;
    if (i < N) {
        int r = rowptr[i] + aux[i >> 10];
        rowptr[i] = r;
        cursor[i] = r;
        dinv[i] = rsqrtf((float)deg[i] + 1.0f);
    }
}

__global__ void k_scatter(const int* __restrict__ src, const int* __restrict__ dst,
                          int* cursor, int* esrc, int E) {
    int e = blockIdx.x * blockDim.x + threadIdx.x;
    if (e >= E) return;
    int s = src[e], d = dst[e];
    int pos = atomicAdd(&cursor[d], 1);
    esrc[pos] = s;
}

// ---------------------------------------------------------------------------
// Tensor-core GEMM (wmma, fp16 x fp16 -> fp32), conflict-free padded tiles.
//   h'[N,Fo](fp16) = (act(in)[N,64] @ W[64,Fo]) * dinv[row]
// Block 0 also zeroes the sentinel feature row.
template <int Fo, bool RELU, typename Tin>
__global__ __launch_bounds__(256) void k_gemm(
    const Tin* __restrict__ in, const float* __restrict__ W,
    const float* __restrict__ dinv, __half* __restrict__ h, int N) {

    constexpr int RB = 128, XP = 72, WP = Fo + 8;
    __shared__ __half sX[RB * XP];
    __shared__ __half sW[64 * WP];
    __shared__ float  sC[8][256];

    int tid = threadIdx.x;
    int warp = tid / 32;
    int lane = tid % 32;

    if (blockIdx.x == 0 && tid < Fo / 8)            // sentinel row -> 0
        *(uint4*)(h + (size_t)SENT * Fo + tid * 8) = make_uint4(0u, 0u, 0u, 0u);

    for (int i = tid * 4; i < 64 * Fo; i += 1024) {
        int r = i / Fo, c = i % Fo;
        float4 v = *(const float4*)(W + i);
        __half2 p0 = __floats2half2_rn(v.x, v.y);
        __half2 p1 = __floats2half2_rn(v.z, v.w);
        *(uint2*)(sW + r * WP + c) = make_uint2(*(unsigned*)&p0, *(unsigned*)&p1);
    }

    int r0 = blockIdx.x * RB;
    int nflt = min(RB, N - r0) * 64;
    const Tin* gin = in + (size_t)r0 * 64;
    for (int i = tid * 4; i < RB * 64; i += 1024) {
        int r = i >> 6, c = i & 63;
        uint2 pk;
        if (i < nflt) {
            if (sizeof(Tin) == 4) {
                float4 v = *(const float4*)((const float*)gin + i);
                if (RELU) {
                    v.x = fmaxf(v.x, 0.0f); v.y = fmaxf(v.y, 0.0f);
                    v.z = fmaxf(v.z, 0.0f); v.w = fmaxf(v.w, 0.0f);
                }
                __half2 p0 = __floats2half2_rn(v.x, v.y);
                __half2 p1 = __floats2half2_rn(v.z, v.w);
                pk = make_uint2(*(unsigned*)&p0, *(unsigned*)&p1);
            } else {
                pk = *(const uint2*)((const __half*)gin + i);
                if (RELU) {
                    __half2 z = __float2half2_rn(0.0f);
                    __half2 a0 = __hmax2(*(__half2*)&pk.x, z);
                    __half2 a1 = __hmax2(*(__half2*)&pk.y, z);
                    pk = make_uint2(*(unsigned*)&a0, *(unsigned*)&a1);
                }
            }
        } else {
            pk = make_uint2(0u, 0u);
        }
        *(uint2*)(sX + r * XP + c) = pk;
    }
    __syncthreads();

    const __half* xw = sX + warp * 16 * XP;
    wmma::fragment<wmma::matrix_a, 16, 16, 16, __half, wmma::row_major> af[4];
#pragma unroll
    for (int k = 0; k < 4; k++)
        wmma::load_matrix_sync(af[k], xw + k * 16, XP);

#pragma unroll
    for (int c = 0; c < Fo / 16; c++) {
        wmma::fragment<wmma::accumulator, 16, 16, 16, float> acc;
        wmma::fill_fragment(acc, 0.0f);
#pragma unroll
        for (int k = 0; k < 4; k++) {
            wmma::fragment<wmma::matrix_b, 16, 16, 16, __half, wmma::row_major> bf;
            wmma::load_matrix_sync(bf, sW + k * 16 * WP + c * 16, WP);
            wmma::mma_sync(acc, af[k], bf, acc);
        }
        wmma::store_matrix_sync(sC[warp], acc, 16, wmma::mem_row_major);
        __syncwarp();
#pragma unroll
        for (int t = 0; t < 2; t++) {
            int idx = t * 32 + lane;
            int row = idx >> 2, colq = idx & 3;
            int gr = r0 + warp * 16 + row;
            if (gr < N) {
                float4 v = *(float4*)(sC[warp] + idx * 4);
                float d = dinv[gr];
                __half2 p0 = __floats2half2_rn(v.x * d, v.y * d);
                __half2 p1 = __floats2half2_rn(v.z * d, v.w * d);
                *(uint2*)(h + (size_t)gr * Fo + c * 16 + colq * 4) =
                    make_uint2(*(unsigned*)&p0, *(unsigned*)&p1);
            }
        }
        __syncwarp();
    }
}

// ---------------------------------------------------------------------------
// Gather-aggregate (padded CSC, remainder-free):
//   a[i] = fp16( bias + dinv[i] * ( h'[i] + sum_j h'[src_j] ) )
template <int F>
__global__ __launch_bounds__(256) void k_agg(
    const __half* __restrict__ h, const int* __restrict__ esrc,
    const int* __restrict__ rowptr, const int* __restrict__ deg,
    const float* __restrict__ dinv, const float* __restrict__ bias,
    __half* __restrict__ out, int N) {

    constexpr int L = F / 8;
    int gid = blockIdx.x * blockDim.x + threadIdx.x;
    int node = gid / L;
    int l = gid % L;
    if (node >= N) return;

    int beg = rowptr[node];
    int rounds = (deg[node] + 7) >> 3;

    float acc[8] = {};

    for (int r = 0; r < rounds; r++) {
        int b = beg + r * 8;
        int s0 = esrc[b + 0];
        int s1 = esrc[b + 1];
        int s2 = esrc[b + 2];
        int s3 = esrc[b + 3];
        int s4 = esrc[b + 4];
        int s5 = esrc[b + 5];
        int s6 = esrc[b + 6];
        int s7 = esrc[b + 7];
        uint4 r0 = *(const uint4*)(h + (size_t)s0 * F + l * 8);
        uint4 r1 = *(const uint4*)(h + (size_t)s1 * F + l * 8);
        uint4 r2 = *(const uint4*)(h + (size_t)s2 * F + l * 8);
        uint4 r3 = *(const uint4*)(h + (size_t)s3 * F + l * 8);
        uint4 r4 = *(const uint4*)(h + (size_t)s4 * F + l * 8);
        uint4 r5 = *(const uint4*)(h + (size_t)s5 * F + l * 8);
        uint4 r6 = *(const uint4*)(h + (size_t)s6 * F + l * 8);
        uint4 r7 = *(const uint4*)(h + (size_t)s7 * F + l * 8);
        const __half2* p0 = (const __half2*)&r0;
        const __half2* p1 = (const __half2*)&r1;
        const __half2* p2 = (const __half2*)&r2;
        const __half2* p3 = (const __half2*)&r3;
        const __half2* p4 = (const __half2*)&r4;
        const __half2* p5 = (const __half2*)&r5;
        const __half2* p6 = (const __half2*)&r6;
        const __half2* p7 = (const __half2*)&r7;
#pragma unroll
        for (int q = 0; q < 4; q++) {
            float2 f0 = __half22float2(p0[q]);
            float2 f1 = __half22float2(p1[q]);
            float2 f2 = __half22float2(p2[q]);
            float2 f3 = __half22float2(p3[q]);
            float2 f4 = __half22float2(p4[q]);
            float2 f5 = __half22float2(p5[q]);
            float2 f6 = __half22float2(p6[q]);
            float2 f7 = __half22float2(p7[q]);
            acc[2*q]   += ((f0.x + f1.x) + (f2.x + f3.x)) + ((f4.x + f5.x) + (f6.x + f7.x));
            acc[2*q+1] += ((f0.y + f1.y) + (f2.y + f3.y)) + ((f4.y + f5.y) + (f6.y + f7.y));
        }
    }

    // self term + scale + bias
    float d = dinv[node];
    uint4 rs = *(const uint4*)(h + (size_t)node * F + l * 8);
    const __half2* ps = (const __half2*)&rs;
    float4 b0 = *(const float4*)(bias + l * 8);
    float4 b1 = *(const float4*)(bias + l * 8 + 4);

    float o[8];
#pragma unroll
    for (int q = 0; q < 4; q++) {
        float2 f = __half22float2(ps[q]);
        o[2*q]   = (acc[2*q]   + f.x) * d;
        o[2*q+1] = (acc[2*q+1] + f.y) * d;
    }
    o[0] += b0.x; o[1] += b0.y; o[2] += b0.z; o[3] += b0.w;
    o[4] += b1.x; o[5] += b1.y; o[6] += b1.z; o[7] += b1.w;

    __half2 q0 = __floats2half2_rn(o[0], o[1]);
    __half2 q1 = __floats2half2_rn(o[2], o[3]);
    __half2 q2 = __floats2half2_rn(o[4], o[5]);
    __half2 q3 = __floats2half2_rn(o[6], o[7]);
    uint4 pk = make_uint4(*(unsigned*)&q0, *(unsigned*)&q1,
                          *(unsigned*)&q2, *(unsigned*)&q3);
    *(uint4*)(out + (size_t)node * F + l * 8) = pk;
}

// ---------------------------------------------------------------------------
#define POOL_NODES 512
__global__ void k_pool(const __half* __restrict__ h, const int* __restrict__ batch,
                       float* __restrict__ sums, int N, int G) {
    __shared__ float sS[MAXG * 32];
    for (int i = threadIdx.x; i < G * 32; i += 256) sS[i] = 0.0f;
    __syncthreads();

    int f = threadIdx.x % 32;
    int w = threadIdx.x / 32;
    int start = blockIdx.x * POOL_NODES;
    int end = min(start + POOL_NODES, N);
    // run-length accumulate (batch sorted) per warp-stripe
    float run = 0.0f;
    int curg = -1;
    for (int n = start + w; n < end; n += 8) {
        int g = batch[n];
        if (g != curg) {
            if (curg >= 0) atomicAdd(&sS[curg * 32 + f], run);
            curg = g; run = 0.0f;
        }
        run += __half2float(h[(size_t)n * 32 + f]);
    }
    if (curg >= 0) atomicAdd(&sS[curg * 32 + f], run);
    __syncthreads();

    for (int i = threadIdx.x; i < G * 32; i += 256)
        if (sS[i] != 0.0f) atomicAdd(&sums[i], sS[i]);
}

__global__ void k_final(const float* __restrict__ sums, const float* __restrict__ cnt,
                        float* __restrict__ out, int G) {
    int i = blockIdx.x * blockDim.x + threadIdx.x;
    if (i < G * 32) out[i] = sums[i] / fmaxf(cnt[i / 32], 1.0f);
}

// ---------------------------------------------------------------------------
extern "C" void kernel_launch(void* const* d_in, const int* in_sizes, int n_in,
                              void* d_out, int out_size) {
    const float* x     = (const float*)d_in[0];
    const int*   ei    = (const int*)d_in[1];
    const int*   batch = (const int*)d_in[2];

    int wi = (n_in >= 10) ? 3 : 2;
    const float* W1 = (const float*)d_in[wi + 1];
    const float* b1 = (const float*)d_in[wi + 2];
    const float* W2 = (const float*)d_in[wi + 3];
    const float* b2 = (const float*)d_in[wi + 4];
    const float* W3 = (const float*)d_in[wi + 5];
    const float* b3 = (const float*)d_in[wi + 6];

    int N = in_sizes[0] / 64;
    int E = in_sizes[1] / 2;
    int G = out_size / 32;
    const int* src = ei;
    const int* dst = ei + E;

    float *p_dinv, *p_sums, *p_cnt;
    __half *p_h, *p_a;
    int *p_deg, *p_rowptr, *p_cursor, *p_aux, *p_esrc;
    cudaGetSymbolAddress((void**)&p_dinv,   g_dinv);
    cudaGetSymbolAddress((void**)&p_deg,    g_deg);
    cudaGetSymbolAddress((void**)&p_rowptr, g_rowptr);
    cudaGetSymbolAddress((void**)&p_cursor, g_cursor);
    cudaGetSymbolAddress((void**)&p_aux,    g_aux);
    cudaGetSymbolAddress((void**)&p_esrc,   g_esrc);
    cudaGetSymbolAddress((void**)&p_h,      g_h);
    cudaGetSymbolAddress((void**)&p_a,      g_a);
    cudaGetSymbolAddress((void**)&p_sums,   g_sums);
    cudaGetSymbolAddress((void**)&p_cnt,    g_cnt);

    float* out = (float*)d_out;
    const int T = 256;
    int nb_scan = (N + 1023) / 1024;
    int nb_node = (N + 127) / 128;

    // --- build padded CSC + norms + graph-size counts ---
    k_zero<<<(PADE + T - 1) / T, T>>>(p_deg, p_sums, p_cnt, p_esrc, N, G);
    k_hist<<<(E + T - 1) / T, T>>>(dst, batch, p_deg, p_cnt, E, N);
    k_scan1<<<nb_scan, 1024>>>(p_deg, p_rowptr, p_aux, N);
    k_scan2<<<1, 128>>>(p_aux, nb_scan);
    k_scan3<<<(N + T - 1) / T, T>>>(p_rowptr, p_cursor, p_aux, p_deg, p_dinv, N);
    k_scatter<<<(E + T - 1) / T, T>>>(src, dst, p_cursor, p_esrc, E);

    // --- layer 1 ---
    k_gemm<64, false, float><<<nb_node, T>>>(x, W1, p_dinv, p_h, N);
    k_agg<64><<<((size_t)N * 8 + T - 1) / T, T>>>(p_h, p_esrc, p_rowptr, p_deg,
                                                  p_dinv, b1, p_a, N);
    // --- layer 2 ---
    k_gemm<64, true, __half><<<nb_node, T>>>(p_a, W2, p_dinv, p_h, N);
    k_agg<64><<<((size_t)N * 8 + T - 1) / T, T>>>(p_h, p_esrc, p_rowptr, p_deg,
                                                  p_dinv, b2, p_a, N);
    // --- layer 3 ---
    k_gemm<32, false, __half><<<nb_node, T>>>(p_a, W3, p_dinv, p_h, N);
    k_agg<32><<<((size_t)N * 4 + T - 1) / T, T>>>(p_h, p_esrc, p_rowptr, p_deg,
                                                  p_dinv, b3, p_a, N);

    // --- pool ---
    k_pool<<<(N + POOL_NODES - 1) / POOL_NODES, T>>>(p_a, batch, p_sums, N, G);
    k_final<<<(G * 32 + T - 1) / T, T>>>(p_sums, p_cnt, out, G);
}

// round 10
// speedup vs baseline: 1.4616x; 1.4616x over previous
#include <cuda_runtime.h>
#include <cuda_fp16.h>
#include <mma.h>

using namespace nvcuda;

#define MAXN 100000
#define MAXE 1600000
#define MAXG 64

__device__ __align__(128) float  g_dinv[MAXN];
__device__ __align__(128) int    g_deg[MAXN];
__device__ __align__(128) int    g_rowptr[MAXN];
__device__ __align__(128) int    g_cursor[MAXN];
__device__ __align__(128) int    g_aux[128];
__device__ __align__(128) int    g_esrc[MAXE];      // CSC: src index per slot
__device__ __align__(128) __half g_h[MAXN * 64];    // pre-scaled fp16 features
__device__ __align__(128) __half g_a[MAXN * 64];    // aggregated activations (fp16)
__device__ __align__(128) float  g_sums[MAXG * 32];
__device__ __align__(128) float  g_cnt[MAXG];

// ---------------------------------------------------------------------------
__global__ void k_zero(int* deg, float* sums, float* cnt, int N, int G) {
    int i = blockIdx.x * blockDim.x + threadIdx.x;
    if (i < N) deg[i] = 0;
    if (i < G * 32) sums[i] = 0.0f;
    if (i < G) cnt[i] = 0.0f;
}

__global__ void k_hist(const int* __restrict__ dst, int* deg, int E) {
    int e = blockIdx.x * blockDim.x + threadIdx.x;
    if (e < E) atomicAdd(&deg[dst[e]], 1);
}

__global__ void k_dinv(const int* __restrict__ deg, float* dinv, int N) {
    int i = blockIdx.x * blockDim.x + threadIdx.x;
    if (i < N) dinv[i] = rsqrtf((float)deg[i] + 1.0f);  // +1 self loop
}

// --- exclusive scan of deg -> rowptr ---------------------------------------
__global__ void k_scan1(const int* __restrict__ deg, int* rowptr, int* aux, int N) {
    __shared__ int s[1024];
    int i = blockIdx.x * 1024 + threadIdx.x;
    int v = (i < N) ? deg[i] : 0;
    s[threadIdx.x] = v;
    __syncthreads();
    for (int off = 1; off < 1024; off <<= 1) {
        int t = (threadIdx.x >= off) ? s[threadIdx.x - off] : 0;
        __syncthreads();
        s[threadIdx.x] += t;
        __syncthreads();
    }
    if (i < N) rowptr[i] = s[threadIdx.x] - v;
    if (threadIdx.x == 1023) aux[blockIdx.x] = s[1023];
}

__global__ void k_scan2(int* aux, int nb) {
    __shared__ int s[128];
    int v = (threadIdx.x < nb) ? aux[threadIdx.x] : 0;
    s[threadIdx.x] = v;
    __syncthreads();
    for (int off = 1; off < 128; off <<= 1) {
        int t = (threadIdx.x >= off) ? s[threadIdx.x - off] : 0;
        __syncthreads();
        s[threadIdx.x] += t;
        __syncthreads();
    }
    if (threadIdx.x < nb) aux[threadIdx.x] = s[threadIdx.x] - v;
}

__global__ void k_scan3(int* rowptr, int* cursor, const int* __restrict__ aux, int N) {
    int i = blockIdx.x * blockDim.x + threadIdx.x;
    if (i < N) {
        int r = rowptr[i] + aux[i >> 10];
        rowptr[i] = r;
        cursor[i] = r;
    }
}

__global__ void k_scatter(const int* __restrict__ src, const int* __restrict__ dst,
                          int* cursor, int* esrc, int E) {
    int e = blockIdx.x * blockDim.x + threadIdx.x;
    if (e >= E) return;
    int s = src[e], d = dst[e];
    int pos = atomicAdd(&cursor[d], 1);
    esrc[pos] = s;
}

// ---------------------------------------------------------------------------
// Tensor-core GEMM (wmma, fp16 x fp16 -> fp32), conflict-free padded tiles.
//   h'[N,Fo](fp16) = (act(in)[N,64] @ W[64,Fo]) * dinv[row]
template <int Fo, bool RELU, typename Tin>
__global__ __launch_bounds__(256) void k_gemm(
    const Tin* __restrict__ in, const float* __restrict__ W,
    const float* __restrict__ dinv, __half* __restrict__ h, int N) {

    constexpr int RB = 128;
    constexpr int XP = 72;          // padded X row pitch (halves)
    constexpr int WP = Fo + 8;      // padded W row pitch

    __shared__ __half sX[RB * XP];      // 18 KB
    __shared__ __half sW[64 * WP];      // <= 9.2 KB
    __shared__ float  sC[8][16 * 16];   // 8 KB staging

    int tid = threadIdx.x;
    int warp = tid / 32;
    int lane = tid % 32;

    // W -> fp16 smem (padded)
    for (int i = tid * 4; i < 64 * Fo; i += 1024) {
        int r = i / Fo, c = i % Fo;
        float4 v = *(const float4*)(W + i);
        __half2 p0 = __floats2half2_rn(v.x, v.y);
        __half2 p1 = __floats2half2_rn(v.z, v.w);
        *(uint2*)(sW + r * WP + c) = make_uint2(*(unsigned*)&p0, *(unsigned*)&p1);
    }

    // X tile -> fp16 smem (padded rows, zero-pad rows beyond N)
    int r0 = blockIdx.x * RB;
    int nrow = min(RB, N - r0);
    int nflt = nrow * 64;
    const Tin* gin = in + (size_t)r0 * 64;
    for (int i = tid * 4; i < RB * 64; i += 1024) {
        int r = i >> 6, c = i & 63;
        uint2 pk;
        if (i < nflt) {
            if (sizeof(Tin) == 4) {
                float4 v = *(const float4*)((const float*)gin + i);
                if (RELU) {
                    v.x = fmaxf(v.x, 0.0f); v.y = fmaxf(v.y, 0.0f);
                    v.z = fmaxf(v.z, 0.0f); v.w = fmaxf(v.w, 0.0f);
                }
                __half2 p0 = __floats2half2_rn(v.x, v.y);
                __half2 p1 = __floats2half2_rn(v.z, v.w);
                pk = make_uint2(*(unsigned*)&p0, *(unsigned*)&p1);
            } else {
                pk = *(const uint2*)((const __half*)gin + i);
                if (RELU) {
                    __half2 z = __float2half2_rn(0.0f);
                    __half2 a0 = __hmax2(*(__half2*)&pk.x, z);
                    __half2 a1 = __hmax2(*(__half2*)&pk.y, z);
                    pk = make_uint2(*(unsigned*)&a0, *(unsigned*)&a1);
                }
            }
        } else {
            pk = make_uint2(0u, 0u);
        }
        *(uint2*)(sX + r * XP + c) = pk;
    }
    __syncthreads();

    const __half* xw = sX + warp * 16 * XP;

    // Hoist A fragments (reused across all column tiles)
    wmma::fragment<wmma::matrix_a, 16, 16, 16, __half, wmma::row_major> af[4];
#pragma unroll
    for (int k = 0; k < 4; k++)
        wmma::load_matrix_sync(af[k], xw + k * 16, XP);

#pragma unroll
    for (int c = 0; c < Fo / 16; c++) {
        wmma::fragment<wmma::accumulator, 16, 16, 16, float> acc;
        wmma::fill_fragment(acc, 0.0f);
#pragma unroll
        for (int k = 0; k < 4; k++) {
            wmma::fragment<wmma::matrix_b, 16, 16, 16, __half, wmma::row_major> bf;
            wmma::load_matrix_sync(bf, sW + k * 16 * WP + c * 16, WP);
            wmma::mma_sync(acc, af[k], bf, acc);
        }
        wmma::store_matrix_sync(sC[warp], acc, 16, wmma::mem_row_major);
        __syncwarp();

        // epilogue: 64 float4s per warp-tile, 2 per lane
#pragma unroll
        for (int t = 0; t < 2; t++) {
            int idx = t * 32 + lane;            // 0..63
            int row = idx >> 2;
            int colq = idx & 3;
            int gr = r0 + warp * 16 + row;
            if (gr < N) {
                float4 v = *(float4*)(sC[warp] + idx * 4);
                float d = dinv[gr];
                __half2 p0 = __floats2half2_rn(v.x * d, v.y * d);
                __half2 p1 = __floats2half2_rn(v.z * d, v.w * d);
                *(uint2*)(h + (size_t)gr * Fo + c * 16 + colq * 4) =
                    make_uint2(*(unsigned*)&p0, *(unsigned*)&p1);
            }
        }
        __syncwarp();
    }
}

// ---------------------------------------------------------------------------
// Gather-aggregate (CSC, pre-scaled fp16, fp32 accumulate, fp16 output):
//   a[i] = fp16( bias + dinv[i] * ( h'[i] + sum_j h'[src_j] ) )
template <int F>
__global__ __launch_bounds__(256) void k_agg(
    const __half* __restrict__ h, const int* __restrict__ esrc,
    const int* __restrict__ rowptr, const int* __restrict__ deg,
    const float* __restrict__ dinv, const float* __restrict__ bias,
    __half* __restrict__ out, int N) {

    constexpr int L = F / 8;
    int gid = blockIdx.x * blockDim.x + threadIdx.x;
    int node = gid / L;
    int l = gid % L;
    if (node >= N) return;

    int beg = rowptr[node];
    int cnt = deg[node];

    float acc[8] = {};

    int j = 0;
    for (; j + 7 < cnt; j += 8) {
        int s0 = esrc[beg + j + 0];
        int s1 = esrc[beg + j + 1];
        int s2 = esrc[beg + j + 2];
        int s3 = esrc[beg + j + 3];
        int s4 = esrc[beg + j + 4];
        int s5 = esrc[beg + j + 5];
        int s6 = esrc[beg + j + 6];
        int s7 = esrc[beg + j + 7];
        uint4 r0 = *(const uint4*)(h + (size_t)s0 * F + l * 8);
        uint4 r1 = *(const uint4*)(h + (size_t)s1 * F + l * 8);
        uint4 r2 = *(const uint4*)(h + (size_t)s2 * F + l * 8);
        uint4 r3 = *(const uint4*)(h + (size_t)s3 * F + l * 8);
        uint4 r4 = *(const uint4*)(h + (size_t)s4 * F + l * 8);
        uint4 r5 = *(const uint4*)(h + (size_t)s5 * F + l * 8);
        uint4 r6 = *(const uint4*)(h + (size_t)s6 * F + l * 8);
        uint4 r7 = *(const uint4*)(h + (size_t)s7 * F + l * 8);
        const __half2* p0 = (const __half2*)&r0;
        const __half2* p1 = (const __half2*)&r1;
        const __half2* p2 = (const __half2*)&r2;
        const __half2* p3 = (const __half2*)&r3;
        const __half2* p4 = (const __half2*)&r4;
        const __half2* p5 = (const __half2*)&r5;
        const __half2* p6 = (const __half2*)&r6;
        const __half2* p7 = (const __half2*)&r7;
#pragma unroll
        for (int q = 0; q < 4; q++) {
            float2 f0 = __half22float2(p0[q]);
            float2 f1 = __half22float2(p1[q]);
            float2 f2 = __half22float2(p2[q]);
            float2 f3 = __half22float2(p3[q]);
            float2 f4 = __half22float2(p4[q]);
            float2 f5 = __half22float2(p5[q]);
            float2 f6 = __half22float2(p6[q]);
            float2 f7 = __half22float2(p7[q]);
            acc[2*q]   += ((f0.x + f1.x) + (f2.x + f3.x)) + ((f4.x + f5.x) + (f6.x + f7.x));
            acc[2*q+1] += ((f0.y + f1.y) + (f2.y + f3.y)) + ((f4.y + f5.y) + (f6.y + f7.y));
        }
    }
    for (; j < cnt; j++) {
        int s = esrc[beg + j];
        uint4 r = *(const uint4*)(h + (size_t)s * F + l * 8);
        const __half2* p = (const __half2*)&r;
#pragma unroll
        for (int q = 0; q < 4; q++) {
            float2 f = __half22float2(p[q]);
            acc[2*q]   += f.x;
            acc[2*q+1] += f.y;
        }
    }

    // self term + scale + bias
    float d = dinv[node];
    uint4 rs = *(const uint4*)(h + (size_t)node * F + l * 8);
    const __half2* ps = (const __half2*)&rs;
    float4 b0 = *(const float4*)(bias + l * 8);
    float4 b1 = *(const float4*)(bias + l * 8 + 4);

    float o[8];
#pragma unroll
    for (int q = 0; q < 4; q++) {
        float2 f = __half22float2(ps[q]);
        o[2*q]   = (acc[2*q]   + f.x) * d;
        o[2*q+1] = (acc[2*q+1] + f.y) * d;
    }
    o[0] += b0.x; o[1] += b0.y; o[2] += b0.z; o[3] += b0.w;
    o[4] += b1.x; o[5] += b1.y; o[6] += b1.z; o[7] += b1.w;

    __half2 q0 = __floats2half2_rn(o[0], o[1]);
    __half2 q1 = __floats2half2_rn(o[2], o[3]);
    __half2 q2 = __floats2half2_rn(o[4], o[5]);
    __half2 q3 = __floats2half2_rn(o[6], o[7]);
    uint4 pk = make_uint4(*(unsigned*)&q0, *(unsigned*)&q1,
                          *(unsigned*)&q2, *(unsigned*)&q3);
    *(uint4*)(out + (size_t)node * F + l * 8) = pk;
}

// ---------------------------------------------------------------------------
#define POOL_NODES 512
__global__ void k_pool(const __half* __restrict__ h, const int* __restrict__ batch,
                       float* __restrict__ sums, float* __restrict__ cnt,
                       int N, int G) {
    __shared__ float sS[MAXG * 32];
    __shared__ float sC[MAXG];
    for (int i = threadIdx.x; i < G * 32; i += 256) sS[i] = 0.0f;
    for (int i = threadIdx.x; i < G; i += 256) sC[i] = 0.0f;
    __syncthreads();

    int f = threadIdx.x % 32;
    int w = threadIdx.x / 32;
    int start = blockIdx.x * POOL_NODES;
    int end = min(start + POOL_NODES, N);
    for (int n = start + w; n < end; n += 8) {
        int g = batch[n];
        atomicAdd(&sS[g * 32 + f], __half2float(h[(size_t)n * 32 + f]));
        if (f == 0) atomicAdd(&sC[g], 1.0f);
    }
    __syncthreads();

    for (int i = threadIdx.x; i < G * 32; i += 256)
        if (sS[i] != 0.0f) atomicAdd(&sums[i], sS[i]);
    for (int i = threadIdx.x; i < G; i += 256)
        if (sC[i] != 0.0f) atomicAdd(&cnt[i], sC[i]);
}

__global__ void k_final(const float* __restrict__ sums, const float* __restrict__ cnt,
                        float* __restrict__ out, int G) {
    int i = blockIdx.x * blockDim.x + threadIdx.x;
    if (i < G * 32) out[i] = sums[i] / fmaxf(cnt[i / 32], 1.0f);
}

// ---------------------------------------------------------------------------
extern "C" void kernel_launch(void* const* d_in, const int* in_sizes, int n_in,
                              void* d_out, int out_size) {
    const float* x     = (const float*)d_in[0];
    const int*   ei    = (const int*)d_in[1];
    const int*   batch = (const int*)d_in[2];

    int wi = (n_in >= 10) ? 3 : 2;
    const float* W1 = (const float*)d_in[wi + 1];
    const float* b1 = (const float*)d_in[wi + 2];
    const float* W2 = (const float*)d_in[wi + 3];
    const float* b2 = (const float*)d_in[wi + 4];
    const float* W3 = (const float*)d_in[wi + 5];
    const float* b3 = (const float*)d_in[wi + 6];

    int N = in_sizes[0] / 64;
    int E = in_sizes[1] / 2;
    int G = out_size / 32;
    const int* src = ei;
    const int* dst = ei + E;

    float *p_dinv, *p_sums, *p_cnt;
    __half *p_h, *p_a;
    int *p_deg, *p_rowptr, *p_cursor, *p_aux, *p_esrc;
    cudaGetSymbolAddress((void**)&p_dinv,   g_dinv);
    cudaGetSymbolAddress((void**)&p_deg,    g_deg);
    cudaGetSymbolAddress((void**)&p_rowptr, g_rowptr);
    cudaGetSymbolAddress((void**)&p_cursor, g_cursor);
    cudaGetSymbolAddress((void**)&p_aux,    g_aux);
    cudaGetSymbolAddress((void**)&p_esrc,   g_esrc);
    cudaGetSymbolAddress((void**)&p_h,      g_h);
    cudaGetSymbolAddress((void**)&p_a,      g_a);
    cudaGetSymbolAddress((void**)&p_sums,   g_sums);
    cudaGetSymbolAddress((void**)&p_cnt,    g_cnt);

    float* out = (float*)d_out;
    const int T = 256;
    int nb_scan = (N + 1023) / 1024;
    int nb_node = (N + 127) / 128;

    // Side stream + events for overlap (created per call; host-side only)
    cudaStream_t s2;
    cudaStreamCreateWithFlags(&s2, cudaStreamNonBlocking);
    cudaEvent_t evHist, evG1;
    cudaEventCreateWithFlags(&evHist, cudaEventDisableTiming);
    cudaEventCreateWithFlags(&evG1, cudaEventDisableTiming);

    // --- main chain: CSC build ---
    k_zero<<<(N + T - 1) / T, T>>>(p_deg, p_sums, p_cnt, N, G);
    k_hist<<<(E + T - 1) / T, T>>>(dst, p_deg, E);
    cudaEventRecord(evHist, 0);

    // --- side chain: dinv + layer-1 GEMM (needs only deg) ---
    cudaStreamWaitEvent(s2, evHist, 0);
    k_dinv<<<(N + T - 1) / T, T, 0, s2>>>(p_deg, p_dinv, N);
    k_gemm<64, false, float><<<nb_node, T, 0, s2>>>(x, W1, p_dinv, p_h, N);
    cudaEventRecord(evG1, s2);

    // --- main chain continues: scan + scatter ---
    k_scan1<<<nb_scan, 1024>>>(p_deg, p_rowptr, p_aux, N);
    k_scan2<<<1, 128>>>(p_aux, nb_scan);
    k_scan3<<<(N + T - 1) / T, T>>>(p_rowptr, p_cursor, p_aux, N);
    k_scatter<<<(E + T - 1) / T, T>>>(src, dst, p_cursor, p_esrc, E);

    // join: agg1 needs both scatter (main) and gemm1 (side)
    cudaStreamWaitEvent(0, evG1, 0);

    // --- layer 1 agg ---
    k_agg<64><<<((size_t)N * 8 + T - 1) / T, T>>>(p_h, p_esrc, p_rowptr, p_deg,
                                                  p_dinv, b1, p_a, N);
    // --- layer 2 ---
    k_gemm<64, true, __half><<<nb_node, T>>>(p_a, W2, p_dinv, p_h, N);
    k_agg<64><<<((size_t)N * 8 + T - 1) / T, T>>>(p_h, p_esrc, p_rowptr, p_deg,
                                                  p_dinv, b2, p_a, N);
    // --- layer 3 ---
    k_gemm<32, false, __half><<<nb_node, T>>>(p_a, W3, p_dinv, p_h, N);
    k_agg<32><<<((size_t)N * 4 + T - 1) / T, T>>>(p_h, p_esrc, p_rowptr, p_deg,
                                                  p_dinv, b3, p_a, N);

    // --- pool ---
    k_pool<<<(N + POOL_NODES - 1) / POOL_NODES, T>>>(p_a, batch, p_sums, p_cnt, N, G);
    k_final<<<(G * 32 + T - 1) / T, T>>>(p_sums, p_cnt, out, G);
}